// round 2
// baseline (speedup 1.0000x reference)
#include <cuda_runtime.h>
#include <cstdint>

// Problem constants (fixed by the reference)
#define B   32
#define D   576
#define L   196
#define CC  10
#define K   256
#define M   (CC * K)          // 2560
#define NW  7                 // ceil(196/32) packed words per (b,d) row
#define MAXSEL 64             // max selected literals per clause (mean ~11.5)

// ---------------- scratch (no allocation allowed) ----------------
__device__ uint32_t      g_litbits[B * D * NW];   // packed literals, 516 KB (fits L2)
__device__ int16_t       g_idx[M * MAXSEL];       // per-clause selected d indices
__device__ int           g_cnt[M];                // per-clause count
__device__ unsigned char g_or[B * M];             // clause_or bits for logits kernel
__device__ int           g_mask_dtype;            // 0=uint8, 1=float32, 2=int32

// ---------------- kernel 0: sniff clause_mask dtype ----------------
// Mask values are 0/1 booleans. Interpreted as 32-bit words:
//   float32 layout -> words are 0x00000000 or 0x3F800000
//   int32   layout -> words are 0x00000000 or 0x00000001
//   uint8   layout -> words are 4 packed bytes each 0x00/0x01 (e.g. 0x00010000)
// These sets are disjoint (beyond {0,1}), so a scan decides unambiguously.
__global__ void detect_kernel(const uint32_t* __restrict__ w, int nwords) {
    __shared__ int s_float, s_multi;
    if (threadIdx.x == 0) { s_float = 0; s_multi = 0; }
    __syncthreads();
    int n = nwords < 16384 ? nwords : 16384;
    for (int i = threadIdx.x; i < n; i += blockDim.x) {
        uint32_t v = w[i];
        if (v == 0x3F800000u) s_float = 1;               // benign race (write 1)
        else if (v != 0u && v != 1u) s_multi = 1;
    }
    __syncthreads();
    if (threadIdx.x == 0)
        g_mask_dtype = s_float ? 1 : (s_multi ? 0 : 2);
}

// ---------------- kernel 1: bit-pack literals over L ----------------
// one warp per (b,d) row; ballot over 32 lanes -> one word; fully coalesced reads
__global__ void pack_kernel(const float* __restrict__ lit) {
    int warp = (blockIdx.x * blockDim.x + threadIdx.x) >> 5;
    int lane = threadIdx.x & 31;
    if (warp >= B * D) return;
    const float* row = lit + (size_t)warp * L;
#pragma unroll
    for (int w = 0; w < NW; ++w) {
        int l = w * 32 + lane;
        bool p = (l < L) ? (row[l] > 0.5f) : false;
        unsigned word = __ballot_sync(0xFFFFFFFFu, p);
        if (lane == 0) g_litbits[warp * NW + w] = word;
    }
}

// ---------------- kernel 2: compact clause masks into index lists ----------------
__global__ void list_kernel(const void* __restrict__ mask) {
    int m = blockIdx.x * blockDim.x + threadIdx.x;
    if (m >= M) return;
    int dt = g_mask_dtype;
    const float*         fm = (const float*)mask         + (size_t)m * D;
    const int*           im = (const int*)mask           + (size_t)m * D;
    const unsigned char* bm = (const unsigned char*)mask + (size_t)m * D;
    int cnt = 0;
    for (int d = 0; d < D; ++d) {
        bool sel;
        if (dt == 1)      sel = (fm[d] != 0.0f);
        else if (dt == 2) sel = (im[d] != 0);
        else              sel = (bm[d] != 0);
        if (sel) {
            if (cnt < MAXSEL) g_idx[m * MAXSEL + cnt] = (int16_t)d;
            ++cnt;
        }
    }
    g_cnt[m] = cnt < MAXSEL ? cnt : MAXSEL;
}

// ---------------- kernel 3: clause AND-reduce + outputs ----------------
// one warp per (b,m). Lanes 0..6 each AND-reduce one packed word over the
// clause's selected d rows (all reads L2-resident). Then shuffle-broadcast and
// write 196 floats coalesced.
__global__ void clause_kernel(float* __restrict__ out_map,
                              float* __restrict__ out_or) {
    int gw   = (blockIdx.x * blockDim.x + threadIdx.x) >> 5;
    int lane = threadIdx.x & 31;
    if (gw >= B * M) return;
    int b = gw / M;
    int m = gw - b * M;

    int cnt = g_cnt[m];
    unsigned acc = 0xFFFFFFFFu;
    if (lane < NW) {
        const uint32_t* base = g_litbits + (size_t)b * D * NW + lane;
        const int16_t*  idx  = g_idx + m * MAXSEL;
        for (int i = 0; i < cnt; ++i) {
            int d = idx[i];
            acc &= base[d * NW];
        }
        if (lane == NW - 1) acc &= 0xFu;   // only 4 valid bits in word 6 (L=196)
    }

    unsigned ws[NW];
#pragma unroll
    for (int w = 0; w < NW; ++w) ws[w] = __shfl_sync(0xFFFFFFFFu, acc, w);

    float* o = out_map + (size_t)gw * L;
#pragma unroll
    for (int w = 0; w < NW; ++w) {
        int l = w * 32 + lane;
        if (l < L) o[l] = (float)((ws[w] >> lane) & 1u);
    }

    if (lane == 0) {
        unsigned any = 0;
#pragma unroll
        for (int w = 0; w < NW; ++w) any |= ws[w];
        out_or[gw]  = any ? 1.0f : 0.0f;
        g_or[gw]    = any ? 1 : 0;
    }
}

// ---------------- kernel 4: weighted vote logits ----------------
// one warp per (b,c); first K/2 clauses positive, second K/2 negative
__global__ void logits_kernel(const float* __restrict__ alpha,
                              float* __restrict__ out_logits) {
    int gw   = (blockIdx.x * blockDim.x + threadIdx.x) >> 5;
    int lane = threadIdx.x & 31;
    if (gw >= B * CC) return;
    int b = gw / CC;
    int c = gw - b * CC;

    float s = 0.0f;
    for (int k = lane; k < K; k += 32) {
        int idx = c * K + k;
        float z = g_or[b * M + idx] ? 1.0f : 0.0f;
        float sg = (k < (K / 2)) ? 1.0f : -1.0f;
        s += z * alpha[idx] * sg;
    }
#pragma unroll
    for (int off = 16; off; off >>= 1) s += __shfl_xor_sync(0xFFFFFFFFu, s, off);
    if (lane == 0) out_logits[gw] = s;
}

// ---------------- launch ----------------
extern "C" void kernel_launch(void* const* d_in, const int* in_sizes, int n_in,
                              void* d_out, int out_size) {
    // Identify inputs by element count (robust to metadata ordering).
    const void* p_lit   = d_in[0];
    const void* p_mask  = d_in[1];
    const void* p_alpha = d_in[2];
    for (int i = 0; i < n_in; ++i) {
        if (in_sizes[i] == B * D * L) p_lit   = d_in[i];
        else if (in_sizes[i] == M * D) p_mask = d_in[i];
        else if (in_sizes[i] == M)     p_alpha = d_in[i];
    }
    const float* literals = (const float*)p_lit;     // [B,D,L]
    const float* alpha    = (const float*)p_alpha;   // [M]

    float* out_map    = (float*)d_out;                 // [B,M,L]
    float* out_or     = out_map + (size_t)B * M * L;   // [B,M]
    float* out_logits = out_or + (size_t)B * M;        // [B,CC]

    // 0) sniff mask dtype (word count safe under all layouts: >=16384 words)
    detect_kernel<<<1, 256>>>((const uint32_t*)p_mask, (M * D) / 4);

    // 1) pack: B*D warps
    {
        int warps = B * D;
        int threads = 256;
        int blocks = (warps * 32 + threads - 1) / threads;
        pack_kernel<<<blocks, threads>>>(literals);
    }
    // 2) clause index lists: M threads
    {
        int threads = 256;
        int blocks = (M + threads - 1) / threads;
        list_kernel<<<blocks, threads>>>(p_mask);
    }
    // 3) clause eval: B*M warps
    {
        int warps = B * M;
        int threads = 256;
        int blocks = (warps * 32 + threads - 1) / threads;
        clause_kernel<<<blocks, threads>>>(out_map, out_or);
    }
    // 4) logits: B*CC warps
    {
        int warps = B * CC;
        int threads = 256;
        int blocks = (warps * 32 + threads - 1) / threads;
        logits_kernel<<<blocks, threads>>>(alpha, out_logits);
    }
}

// round 3
// speedup vs baseline: 3.2020x; 3.2020x over previous
#include <cuda_runtime.h>
#include <cstdint>

// Problem constants (fixed by the reference)
#define B   32
#define D   576
#define L   196
#define CC  10
#define K   256
#define M   (CC * K)          // 2560
#define NW  7                 // ceil(196/32) packed words per (b,d) row
#define MAXSEL 64             // max selected literals per clause (mean ~11.5)

// ---------------- scratch (no allocation allowed) ----------------
__device__ uint32_t      g_litbits[B * D * NW];   // packed literals, 516 KB (L2-resident)
__device__ int16_t       g_idx[M * MAXSEL];       // per-clause selected d indices (padded)
__device__ int           g_cnt[M];                // per-clause count, rounded up to mult of 4
__device__ unsigned char g_or[B * M];             // clause_or bits for logits kernel
__device__ int           g_mask_dtype;            // 0=uint8, 1=float32, 2=int32

// ---------------- kernel 0: sniff clause_mask dtype ----------------
//   float32 layout -> words are 0x00000000 or 0x3F800000
//   int32   layout -> words are 0x00000000 or 0x00000001
//   uint8   layout -> words are 4 packed 0x00/0x01 bytes (values outside {0,1})
__global__ void detect_kernel(const uint32_t* __restrict__ w, int nwords) {
    __shared__ int s_float, s_multi;
    if (threadIdx.x == 0) { s_float = 0; s_multi = 0; }
    __syncthreads();
    int n = nwords < 4096 ? nwords : 4096;
    for (int i = threadIdx.x; i < n; i += blockDim.x) {
        uint32_t v = w[i];
        if (v == 0x3F800000u) s_float = 1;               // benign race
        else if (v != 0u && v != 1u) s_multi = 1;
    }
    __syncthreads();
    if (threadIdx.x == 0)
        g_mask_dtype = s_float ? 1 : (s_multi ? 0 : 2);
}

// ---------------- kernel 1: bit-pack literals over L ----------------
// one warp per (b,d) row; ballot over 32 lanes -> one word; coalesced reads
__global__ void pack_kernel(const float* __restrict__ lit) {
    int warp = (blockIdx.x * blockDim.x + threadIdx.x) >> 5;
    int lane = threadIdx.x & 31;
    if (warp >= B * D) return;
    const float* row = lit + (size_t)warp * L;
#pragma unroll
    for (int w = 0; w < NW; ++w) {
        int l = w * 32 + lane;
        bool p = (l < L) ? (row[l] > 0.5f) : false;
        unsigned word = __ballot_sync(0xFFFFFFFFu, p);
        if (lane == 0) g_litbits[warp * NW + w] = word;
    }
}

// ---------------- kernel 2: compact clause masks (warp per clause) ----------------
// Coalesced row read in 32-wide chunks; ballot+popc compaction into g_idx.
// Pads the index list to a multiple of 4 with the first selected index
// (AND is idempotent), so the clause kernel can run an unpredicated x4 loop.
__global__ void list_kernel(const void* __restrict__ mask) {
    int m    = (blockIdx.x * blockDim.x + threadIdx.x) >> 5;
    int lane = threadIdx.x & 31;
    if (m >= M) return;
    int dt = g_mask_dtype;
    const float*         fm = (const float*)mask         + (size_t)m * D;
    const int*           im = (const int*)mask           + (size_t)m * D;
    const unsigned char* bm = (const unsigned char*)mask + (size_t)m * D;

    int cnt = 0;
    int firstd = -1;
#pragma unroll 2
    for (int c = 0; c < D; c += 32) {                 // D=576 -> 18 chunks, no tail
        int d = c + lane;
        bool sel;
        if (dt == 1)      sel = (fm[d] != 0.0f);
        else if (dt == 2) sel = (im[d] != 0);
        else              sel = (bm[d] != 0);
        unsigned bal = __ballot_sync(0xFFFFFFFFu, sel);
        if (firstd < 0 && bal) firstd = c + __ffs(bal) - 1;   // uniform across warp
        int pos = cnt + __popc(bal & ((1u << lane) - 1u));
        if (sel && pos < MAXSEL) g_idx[m * MAXSEL + pos] = (int16_t)d;
        cnt += __popc(bal);
    }
    if (cnt > MAXSEL) cnt = MAXSEL;
    int cnt4 = (cnt + 3) & ~3;                        // <= MAXSEL (64 mult of 4)
    // pad with first selected index (idempotent under AND)
    if (lane < cnt4 - cnt) g_idx[m * MAXSEL + cnt + lane] = (int16_t)firstd;
    if (lane == 0) g_cnt[m] = cnt4;
}

// ---------------- kernel 3: clause AND-reduce + outputs ----------------
// One warp handles clause m for FOUR batches. Lane layout: lanes 0..27 =
// (bq in 0..3) x (w in 0..6); lanes 28..31 idle in the gather.
// Gather loop consumes 4 packed idx per iteration (uint64 load, unpredicated
// thanks to idempotent padding). Stores are float4 (2 STG.128 per row).
__global__ void clause_kernel(float* __restrict__ out_map,
                              float* __restrict__ out_or) {
    int warp_in_blk = threadIdx.x >> 5;
    int lane        = threadIdx.x & 31;
    int m  = blockIdx.x * 8 + warp_in_blk;            // 320 blocks x 8 warps = 2560
    int b0 = blockIdx.y * 4;                          // 8 y-blocks x 4 batches = 32

    int bq = lane / 7;                                // 0..4 (4 for lanes 28..31)
    int w  = lane - bq * 7;

    int cnt4 = g_cnt[m];
    const int16_t* idxp = g_idx + m * MAXSEL;

    unsigned acc = 0xFFFFFFFFu;
    if (lane < 28) {
        const uint32_t* base = g_litbits + (size_t)(b0 + bq) * (D * NW) + w;
        for (int i = 0; i < cnt4; i += 4) {
            uint64_t q = *(const uint64_t*)(idxp + i);
            int d0 = (int)(q & 0xFFFFu);
            int d1 = (int)((q >> 16) & 0xFFFFu);
            int d2 = (int)((q >> 32) & 0xFFFFu);
            int d3 = (int)((q >> 48) & 0xFFFFu);
            unsigned a0 = base[d0 * NW];
            unsigned a1 = base[d1 * NW];
            unsigned a2 = base[d2 * NW];
            unsigned a3 = base[d3 * NW];
            acc &= (a0 & a1) & (a2 & a3);
        }
        if (w == 6) acc &= 0xFu;                      // 4 valid bits in word 6
    }

    // ---- clause_map stores: per batch row, 49 float4 slots (196 floats) ----
#pragma unroll
    for (int q = 0; q < 4; ++q) {
        uint4* row = (uint4*)(out_map + ((size_t)(b0 + q) * M + m) * L);
        // pass 1: slots 0..31  (words 0..3)
        unsigned w0 = __shfl_sync(0xFFFFFFFFu, acc, q * 7 + (lane >> 3));
        unsigned n0 = (w0 >> ((lane & 7) * 4)) & 0xFu;
        uint4 v;
        v.x = (n0 & 1u)        * 0x3F800000u;
        v.y = ((n0 >> 1) & 1u) * 0x3F800000u;
        v.z = ((n0 >> 2) & 1u) * 0x3F800000u;
        v.w = ((n0 >> 3) & 1u) * 0x3F800000u;
        row[lane] = v;
        // pass 2: slots 32..48 (words 4..6), lanes 0..16
        unsigned w1 = __shfl_sync(0xFFFFFFFFu, acc, q * 7 + 4 + (lane >> 3));
        if (lane < 17) {
            unsigned n1 = (w1 >> ((lane & 7) * 4)) & 0xFu;
            uint4 u;
            u.x = (n1 & 1u)        * 0x3F800000u;
            u.y = ((n1 >> 1) & 1u) * 0x3F800000u;
            u.z = ((n1 >> 2) & 1u) * 0x3F800000u;
            u.w = ((n1 >> 3) & 1u) * 0x3F800000u;
            row[32 + lane] = u;
        }
    }

    // ---- clause_or ----
    bool nz = (lane < 28) && (acc != 0u);
    unsigned bal = __ballot_sync(0xFFFFFFFFu, nz);
    if (lane < 4) {
        unsigned any = (bal >> (lane * 7)) & 0x7Fu;
        int gi = (b0 + lane) * M + m;
        out_or[gi] = any ? 1.0f : 0.0f;
        g_or[gi]   = any ? 1 : 0;
    }
}

// ---------------- kernel 4: weighted vote logits ----------------
__global__ void logits_kernel(const float* __restrict__ alpha,
                              float* __restrict__ out_logits) {
    int gw   = (blockIdx.x * blockDim.x + threadIdx.x) >> 5;
    int lane = threadIdx.x & 31;
    if (gw >= B * CC) return;
    int b = gw / CC;
    int c = gw - b * CC;

    float s = 0.0f;
    for (int k = lane; k < K; k += 32) {
        int idx = c * K + k;
        float z = g_or[b * M + idx] ? 1.0f : 0.0f;
        float sg = (k < (K / 2)) ? 1.0f : -1.0f;
        s += z * alpha[idx] * sg;
    }
#pragma unroll
    for (int off = 16; off; off >>= 1) s += __shfl_xor_sync(0xFFFFFFFFu, s, off);
    if (lane == 0) out_logits[gw] = s;
}

// ---------------- launch ----------------
extern "C" void kernel_launch(void* const* d_in, const int* in_sizes, int n_in,
                              void* d_out, int out_size) {
    const void* p_lit   = d_in[0];
    const void* p_mask  = d_in[1];
    const void* p_alpha = d_in[2];
    for (int i = 0; i < n_in; ++i) {
        if (in_sizes[i] == B * D * L)  p_lit   = d_in[i];
        else if (in_sizes[i] == M * D) p_mask  = d_in[i];
        else if (in_sizes[i] == M)     p_alpha = d_in[i];
    }
    const float* literals = (const float*)p_lit;
    const float* alpha    = (const float*)p_alpha;

    float* out_map    = (float*)d_out;                 // [B,M,L]
    float* out_or     = out_map + (size_t)B * M * L;   // [B,M]
    float* out_logits = out_or + (size_t)B * M;        // [B,CC]

    detect_kernel<<<1, 256>>>((const uint32_t*)p_mask, (M * D) / 4);

    {   // pack: B*D warps
        int warps = B * D;
        pack_kernel<<<(warps * 32 + 255) / 256, 256>>>(literals);
    }
    {   // clause index lists: M warps
        list_kernel<<<(M * 32 + 255) / 256, 256>>>(p_mask);
    }
    {   // clause eval: (M/8) x (B/4) blocks, 8 warps each
        dim3 grid(M / 8, B / 4);
        clause_kernel<<<grid, 256>>>(out_map, out_or);
    }
    {   // logits: B*CC warps
        int warps = B * CC;
        logits_kernel<<<(warps * 32 + 255) / 256, 256>>>(alpha, out_logits);
    }
}

// round 4
// speedup vs baseline: 3.8424x; 1.2000x over previous
#include <cuda_runtime.h>
#include <cstdint>

// Problem constants (fixed by the reference)
#define B   32
#define D   576
#define L   196
#define CC  10
#define K   256
#define M   (CC * K)          // 2560
#define NW  7                 // valid packed words per (b,d) row
#define NWP 8                 // padded words (for [d][b][8] layout)
#define MAXSEL 64             // max selected literals per clause (mean ~11.5)

// prep kernel block roles
#define LIST_BLOCKS   (M / 8)                 // 320 (8 warps/block, warp per clause)
#define PACK_WARPS    (B * D)                 // 18432
#define PACK_BLOCKS   (PACK_WARPS / 8)        // 2304
#define PREP_BLOCKS   (1 + LIST_BLOCKS + PACK_BLOCKS)

// ---------------- scratch (no allocation allowed) ----------------
// litbits layout: word index = d*(B*NWP) + b*NWP + w   -> gathers hit ONE line
__device__ uint32_t      g_litbits[D * B * NWP];  // 576 KB (L2-resident)
__device__ int16_t       g_idx[M * MAXSEL];       // per-clause selected d (padded)
__device__ int           g_cnt[M];                // per-clause count (mult of 4)
__device__ unsigned char g_or[B * M];             // clause_or bits for logits
__device__ int           g_mask_dtype;            // 0=uint8, 1=float32, 2=int32
__device__ volatile int  g_dt_ready;              // detect-done flag (monotonic)

// ---------------- kernel 1: fused prep (detect | list | pack) ----------------
// block 0            : dtype detect (writes g_mask_dtype, then g_dt_ready=1)
// blocks 1..320      : clause-mask compaction (spin on g_dt_ready; block 0 is
//                      wave-1 resident so no deadlock; flag/value are
//                      input-deterministic across graph replays)
// blocks 321..2624   : literal bit-pack into transposed layout
__global__ void prep_kernel(const float* __restrict__ lit,
                            const void*  __restrict__ mask) {
    int lane = threadIdx.x & 31;
    int wblk = threadIdx.x >> 5;

    if (blockIdx.x == 0) {
        // ---- detect: mask values are 0/1 booleans; as 32-bit words:
        //   float32 -> {0, 0x3F800000}; int32 -> {0,1}; uint8 -> packed bytes
        __shared__ int s_float, s_multi;
        if (threadIdx.x == 0) { s_float = 0; s_multi = 0; }
        __syncthreads();
        const uint32_t* w = (const uint32_t*)mask;
        for (int i = threadIdx.x; i < 4096; i += blockDim.x) {
            uint32_t v = w[i];
            if (v == 0x3F800000u) s_float = 1;            // benign race
            else if (v != 0u && v != 1u) s_multi = 1;
        }
        __syncthreads();
        if (threadIdx.x == 0) {
            g_mask_dtype = s_float ? 1 : (s_multi ? 0 : 2);
            __threadfence();
            g_dt_ready = 1;
        }
        return;
    }

    if (blockIdx.x <= LIST_BLOCKS) {
        // ---- list: warp per clause, coalesced chunks + ballot/popc compaction
        int m = (blockIdx.x - 1) * 8 + wblk;
        while (g_dt_ready == 0) { __nanosleep(64); }
        __threadfence();
        int dt = g_mask_dtype;
        const float*         fm = (const float*)mask         + (size_t)m * D;
        const int*           im = (const int*)mask           + (size_t)m * D;
        const unsigned char* bm = (const unsigned char*)mask + (size_t)m * D;

        int cnt = 0;
        int firstd = -1;
        for (int c = 0; c < D; c += 32) {                 // 18 chunks, no tail
            int d = c + lane;
            bool sel;
            if (dt == 1)      sel = (fm[d] != 0.0f);
            else if (dt == 2) sel = (im[d] != 0);
            else              sel = (bm[d] != 0);
            unsigned bal = __ballot_sync(0xFFFFFFFFu, sel);
            if (firstd < 0 && bal) firstd = c + __ffs(bal) - 1;
            int pos = cnt + __popc(bal & ((1u << lane) - 1u));
            if (sel && pos < MAXSEL) g_idx[m * MAXSEL + pos] = (int16_t)d;
            cnt += __popc(bal);
        }
        if (cnt > MAXSEL) cnt = MAXSEL;
        int cnt4 = (cnt + 3) & ~3;
        if (lane < cnt4 - cnt) g_idx[m * MAXSEL + cnt + lane] = (int16_t)firstd;
        if (lane == 0) g_cnt[m] = cnt4;
        return;
    }

    // ---- pack: warp per (b,d) row; transposed store [d][b][8]
    int pw = (blockIdx.x - 1 - LIST_BLOCKS) * 8 + wblk;   // 0 .. B*D-1
    int b = pw / D;
    int d = pw - b * D;
    const float* row = lit + (size_t)pw * L;
    unsigned ws[NW];
#pragma unroll
    for (int w = 0; w < NW; ++w) {
        int l = w * 32 + lane;
        bool p = (l < L) ? (row[l] > 0.5f) : false;
        ws[w] = __ballot_sync(0xFFFFFFFFu, p);
    }
    // lanes 0..6 store the 7 words coalesced (28B contiguous)
    unsigned v = ws[0];
    if (lane == 1) v = ws[1];
    if (lane == 2) v = ws[2];
    if (lane == 3) v = ws[3];
    if (lane == 4) v = ws[4];
    if (lane == 5) v = ws[5];
    if (lane == 6) v = ws[6];
    if (lane < NW) g_litbits[d * (B * NWP) + b * NWP + lane] = v;
}

// ---------------- kernel 2: clause AND-reduce + outputs ----------------
// One warp: clause m x 4 batches. Lanes 0..27 = (bq 0..3) x (w 0..6).
// Each gather LDG (28 lanes) hits exactly one 128B line of g_litbits.
__global__ void clause_kernel(float* __restrict__ out_map,
                              float* __restrict__ out_or) {
    int wblk = threadIdx.x >> 5;
    int lane = threadIdx.x & 31;
    int m  = blockIdx.x * 8 + wblk;                   // 320 x 8 = 2560
    int b0 = blockIdx.y * 4;                          // 8 x 4 = 32

    int bq = lane / 7;                                // 0..4 (4 => idle)
    int w  = lane - bq * 7;

    int cnt4 = g_cnt[m];
    const int16_t* idxp = g_idx + m * MAXSEL;

    unsigned acc = 0xFFFFFFFFu;
    if (lane < 28) {
        const uint32_t* base = g_litbits + (b0 + bq) * NWP + w;
        for (int i = 0; i < cnt4; i += 4) {
            uint64_t q = *(const uint64_t*)(idxp + i);
            int d0 = (int)(q & 0xFFFFu);
            int d1 = (int)((q >> 16) & 0xFFFFu);
            int d2 = (int)((q >> 32) & 0xFFFFu);
            int d3 = (int)((q >> 48) & 0xFFFFu);
            unsigned a0 = base[d0 * (B * NWP)];
            unsigned a1 = base[d1 * (B * NWP)];
            unsigned a2 = base[d2 * (B * NWP)];
            unsigned a3 = base[d3 * (B * NWP)];
            acc &= (a0 & a1) & (a2 & a3);
        }
        if (w == 6) acc &= 0xFu;                      // 4 valid bits in word 6
    }

    // ---- clause_map stores: per batch row, 49 float4 slots ----
#pragma unroll
    for (int q = 0; q < 4; ++q) {
        uint4* row = (uint4*)(out_map + ((size_t)(b0 + q) * M + m) * L);
        unsigned w0 = __shfl_sync(0xFFFFFFFFu, acc, q * 7 + (lane >> 3));
        unsigned n0 = (w0 >> ((lane & 7) * 4)) & 0xFu;
        uint4 v;
        v.x = (n0 & 1u)        * 0x3F800000u;
        v.y = ((n0 >> 1) & 1u) * 0x3F800000u;
        v.z = ((n0 >> 2) & 1u) * 0x3F800000u;
        v.w = ((n0 >> 3) & 1u) * 0x3F800000u;
        row[lane] = v;
        unsigned w1 = __shfl_sync(0xFFFFFFFFu, acc, q * 7 + 4 + (lane >> 3));
        if (lane < 17) {
            unsigned n1 = (w1 >> ((lane & 7) * 4)) & 0xFu;
            uint4 u;
            u.x = (n1 & 1u)        * 0x3F800000u;
            u.y = ((n1 >> 1) & 1u) * 0x3F800000u;
            u.z = ((n1 >> 2) & 1u) * 0x3F800000u;
            u.w = ((n1 >> 3) & 1u) * 0x3F800000u;
            row[32 + lane] = u;
        }
    }

    // ---- clause_or ----
    bool nz = (lane < 28) && (acc != 0u);
    unsigned bal = __ballot_sync(0xFFFFFFFFu, nz);
    if (lane < 4) {
        unsigned any = (bal >> (lane * 7)) & 0x7Fu;
        int gi = (b0 + lane) * M + m;
        out_or[gi] = any ? 1.0f : 0.0f;
        g_or[gi]   = any ? 1 : 0;
    }
}

// ---------------- kernel 3: weighted vote logits ----------------
__global__ void logits_kernel(const float* __restrict__ alpha,
                              float* __restrict__ out_logits) {
    int gw   = (blockIdx.x * blockDim.x + threadIdx.x) >> 5;
    int lane = threadIdx.x & 31;
    if (gw >= B * CC) return;
    int b = gw / CC;
    int c = gw - b * CC;

    float s = 0.0f;
    for (int k = lane; k < K; k += 32) {
        int idx = c * K + k;
        float z = g_or[b * M + idx] ? 1.0f : 0.0f;
        float sg = (k < (K / 2)) ? 1.0f : -1.0f;
        s += z * alpha[idx] * sg;
    }
#pragma unroll
    for (int off = 16; off; off >>= 1) s += __shfl_xor_sync(0xFFFFFFFFu, s, off);
    if (lane == 0) out_logits[gw] = s;
}

// ---------------- launch ----------------
extern "C" void kernel_launch(void* const* d_in, const int* in_sizes, int n_in,
                              void* d_out, int out_size) {
    const void* p_lit   = d_in[0];
    const void* p_mask  = d_in[1];
    const void* p_alpha = d_in[2];
    for (int i = 0; i < n_in; ++i) {
        if (in_sizes[i] == B * D * L)  p_lit   = d_in[i];
        else if (in_sizes[i] == M * D) p_mask  = d_in[i];
        else if (in_sizes[i] == M)     p_alpha = d_in[i];
    }
    const float* literals = (const float*)p_lit;
    const float* alpha    = (const float*)p_alpha;

    float* out_map    = (float*)d_out;                 // [B,M,L]
    float* out_or     = out_map + (size_t)B * M * L;   // [B,M]
    float* out_logits = out_or + (size_t)B * M;        // [B,CC]

    prep_kernel<<<PREP_BLOCKS, 256>>>(literals, p_mask);

    dim3 cgrid(M / 8, B / 4);
    clause_kernel<<<cgrid, 256>>>(out_map, out_or);

    int lw = B * CC;
    logits_kernel<<<(lw * 32 + 255) / 256, 256>>>(alpha, out_logits);
}

// round 5
// speedup vs baseline: 3.8804x; 1.0099x over previous
#include <cuda_runtime.h>
#include <cstdint>

// Problem constants (fixed by the reference)
#define B   32
#define D   576
#define L   196
#define CC  10
#define K   256
#define M   (CC * K)          // 2560
#define NW  7                 // valid packed words per (b,d) row
#define NWP 8                 // padded words (for [d][b][8] layout)
#define MAXSEL 64             // max selected literals per clause (mean ~11.5)

#define ROWS_PER_WARP 8
// prep kernel block roles
#define LIST_BLOCKS   (M / 8)                                  // 320
#define PACK_WARPS    ((B * D) / ROWS_PER_WARP)                // 2304
#define PACK_BLOCKS   (PACK_WARPS / 8)                         // 288
#define PREP_BLOCKS   (1 + LIST_BLOCKS + PACK_BLOCKS)          // 609 (~1 wave)

// ---------------- scratch (no allocation allowed) ----------------
// litbits layout: word index = d*(B*NWP) + b*NWP + w  -> clause gathers hit ONE line
__device__ uint32_t      g_litbits[D * B * NWP];  // 576 KB (L2-resident)
__device__ int16_t       g_idx[M * MAXSEL];       // per-clause selected d (padded)
__device__ int           g_cnt[M];                // per-clause count (mult of 4)
__device__ unsigned char g_or[B * M];             // clause_or bits for logits
__device__ int           g_mask_dtype;            // 0=uint8, 1=float32, 2=int32
__device__ volatile int  g_dt_ready;              // detect-done flag (monotonic)

// ---------------- kernel 1: fused prep (detect | list | pack) ----------------
__global__ void __launch_bounds__(256) prep_kernel(const float* __restrict__ lit,
                                                   const void*  __restrict__ mask) {
    int lane = threadIdx.x & 31;
    int wblk = threadIdx.x >> 5;

    if (blockIdx.x == 0) {
        // ---- detect: mask values are 0/1 booleans; as 32-bit words:
        //   float32 -> {0, 0x3F800000}; int32 -> {0,1}; uint8 -> packed bytes
        __shared__ int s_float, s_multi;
        if (threadIdx.x == 0) { s_float = 0; s_multi = 0; }
        __syncthreads();
        const uint32_t* w = (const uint32_t*)mask;
        for (int i = threadIdx.x; i < 4096; i += blockDim.x) {
            uint32_t v = w[i];
            if (v == 0x3F800000u) s_float = 1;            // benign race
            else if (v != 0u && v != 1u) s_multi = 1;
        }
        __syncthreads();
        if (threadIdx.x == 0) {
            g_mask_dtype = s_float ? 1 : (s_multi ? 0 : 2);
            __threadfence();
            g_dt_ready = 1;
        }
        return;
    }

    if (blockIdx.x <= LIST_BLOCKS) {
        // ---- list: warp per clause; coalesced chunks + ballot/popc compaction.
        // Spin on detect flag (block 0 is wave-1 resident -> no deadlock; the
        // flag value is input-deterministic across graph replays).
        int m = (blockIdx.x - 1) * 8 + wblk;
        while (g_dt_ready == 0) { __nanosleep(64); }
        __threadfence();
        int dt = g_mask_dtype;
        const float*         fm = (const float*)mask         + (size_t)m * D;
        const int*           im = (const int*)mask           + (size_t)m * D;
        const unsigned char* bm = (const unsigned char*)mask + (size_t)m * D;

        int cnt = 0;
        int firstd = -1;
        for (int c = 0; c < D; c += 32) {                 // 18 chunks, no tail
            int d = c + lane;
            bool sel;
            if (dt == 1)      sel = (fm[d] != 0.0f);
            else if (dt == 2) sel = (im[d] != 0);
            else              sel = (bm[d] != 0);
            unsigned bal = __ballot_sync(0xFFFFFFFFu, sel);
            if (firstd < 0 && bal) firstd = c + __ffs(bal) - 1;
            int pos = cnt + __popc(bal & ((1u << lane) - 1u));
            if (sel && pos < MAXSEL) g_idx[m * MAXSEL + pos] = (int16_t)d;
            cnt += __popc(bal);
        }
        if (cnt > MAXSEL) cnt = MAXSEL;
        int cnt4 = (cnt + 3) & ~3;
        if (lane < cnt4 - cnt) g_idx[m * MAXSEL + cnt + lane] = (int16_t)firstd;
        if (lane == 0) g_cnt[m] = cnt4;
        return;
    }

    // ---- pack: warp handles ROWS_PER_WARP consecutive (b,d) rows with
    // register double-buffering: row r+1's loads issue before row r's ballots,
    // hiding the DRAM latency chain. Transposed store layout [d][b][8].
    int pw   = (blockIdx.x - 1 - LIST_BLOCKS) * 8 + wblk;     // 0 .. PACK_WARPS-1
    int row0 = pw * ROWS_PER_WARP;                            // (b*D + d) index
    int b = row0 / D;
    int d = row0 - b * D;

    const float* rp = lit + (size_t)row0 * L;
    float cur[NW];
#pragma unroll
    for (int w = 0; w < NW; ++w) {
        int l = w * 32 + lane;
        cur[w] = (l < L) ? rp[l] : 0.0f;
    }

#pragma unroll
    for (int r = 0; r < ROWS_PER_WARP; ++r) {
        float nxt[NW];
        if (r < ROWS_PER_WARP - 1) {
            const float* np = rp + (size_t)(r + 1) * L;
#pragma unroll
            for (int w = 0; w < NW; ++w) {
                int l = w * 32 + lane;
                nxt[w] = (l < L) ? np[l] : 0.0f;
            }
        }
        unsigned ws[NW];
#pragma unroll
        for (int w = 0; w < NW; ++w)
            ws[w] = __ballot_sync(0xFFFFFFFFu, cur[w] > 0.5f);

        // lanes 0..6 store the 7 words coalesced (28B contiguous)
        unsigned v = ws[0];
        if (lane == 1) v = ws[1];
        if (lane == 2) v = ws[2];
        if (lane == 3) v = ws[3];
        if (lane == 4) v = ws[4];
        if (lane == 5) v = ws[5];
        if (lane == 6) v = ws[6];
        if (lane < NW) g_litbits[d * (B * NWP) + b * NWP + lane] = v;

        // advance (b,d) and buffers
        if (++d == D) { d = 0; ++b; }
#pragma unroll
        for (int w = 0; w < NW; ++w) cur[w] = nxt[w];
    }
}

// ---------------- kernel 2: clause AND-reduce + outputs ----------------
// One warp: clause m x 4 batches. Lanes 0..27 = (bq 0..3) x (w 0..6).
// Each gather LDG (28 lanes) hits exactly one 128B line of g_litbits.
__global__ void clause_kernel(float* __restrict__ out_map,
                              float* __restrict__ out_or) {
    int wblk = threadIdx.x >> 5;
    int lane = threadIdx.x & 31;
    int m  = blockIdx.x * 8 + wblk;                   // 320 x 8 = 2560
    int b0 = blockIdx.y * 4;                          // 8 x 4 = 32

    int bq = lane / 7;                                // 0..4 (4 => idle)
    int w  = lane - bq * 7;

    int cnt4 = g_cnt[m];
    const int16_t* idxp = g_idx + m * MAXSEL;

    unsigned acc = 0xFFFFFFFFu;
    if (lane < 28) {
        const uint32_t* base = g_litbits + (b0 + bq) * NWP + w;
        for (int i = 0; i < cnt4; i += 4) {
            uint64_t q = *(const uint64_t*)(idxp + i);
            int d0 = (int)(q & 0xFFFFu);
            int d1 = (int)((q >> 16) & 0xFFFFu);
            int d2 = (int)((q >> 32) & 0xFFFFu);
            int d3 = (int)((q >> 48) & 0xFFFFu);
            unsigned a0 = base[d0 * (B * NWP)];
            unsigned a1 = base[d1 * (B * NWP)];
            unsigned a2 = base[d2 * (B * NWP)];
            unsigned a3 = base[d3 * (B * NWP)];
            acc &= (a0 & a1) & (a2 & a3);
        }
        if (w == 6) acc &= 0xFu;                      // 4 valid bits in word 6
    }

    // ---- clause_map stores: per batch row, 49 float4 slots ----
#pragma unroll
    for (int q = 0; q < 4; ++q) {
        uint4* row = (uint4*)(out_map + ((size_t)(b0 + q) * M + m) * L);
        unsigned w0 = __shfl_sync(0xFFFFFFFFu, acc, q * 7 + (lane >> 3));
        unsigned n0 = (w0 >> ((lane & 7) * 4)) & 0xFu;
        uint4 v;
        v.x = (n0 & 1u)        * 0x3F800000u;
        v.y = ((n0 >> 1) & 1u) * 0x3F800000u;
        v.z = ((n0 >> 2) & 1u) * 0x3F800000u;
        v.w = ((n0 >> 3) & 1u) * 0x3F800000u;
        row[lane] = v;
        unsigned w1 = __shfl_sync(0xFFFFFFFFu, acc, q * 7 + 4 + (lane >> 3));
        if (lane < 17) {
            unsigned n1 = (w1 >> ((lane & 7) * 4)) & 0xFu;
            uint4 u;
            u.x = (n1 & 1u)        * 0x3F800000u;
            u.y = ((n1 >> 1) & 1u) * 0x3F800000u;
            u.z = ((n1 >> 2) & 1u) * 0x3F800000u;
            u.w = ((n1 >> 3) & 1u) * 0x3F800000u;
            row[32 + lane] = u;
        }
    }

    // ---- clause_or ----
    bool nz = (lane < 28) && (acc != 0u);
    unsigned bal = __ballot_sync(0xFFFFFFFFu, nz);
    if (lane < 4) {
        unsigned any = (bal >> (lane * 7)) & 0x7Fu;
        int gi = (b0 + lane) * M + m;
        out_or[gi] = any ? 1.0f : 0.0f;
        g_or[gi]   = any ? 1 : 0;
    }
}

// ---------------- kernel 3: weighted vote logits ----------------
__global__ void logits_kernel(const float* __restrict__ alpha,
                              float* __restrict__ out_logits) {
    int gw   = (blockIdx.x * blockDim.x + threadIdx.x) >> 5;
    int lane = threadIdx.x & 31;
    if (gw >= B * CC) return;
    int b = gw / CC;
    int c = gw - b * CC;

    float s = 0.0f;
    for (int k = lane; k < K; k += 32) {
        int idx = c * K + k;
        float z = g_or[b * M + idx] ? 1.0f : 0.0f;
        float sg = (k < (K / 2)) ? 1.0f : -1.0f;
        s += z * alpha[idx] * sg;
    }
#pragma unroll
    for (int off = 16; off; off >>= 1) s += __shfl_xor_sync(0xFFFFFFFFu, s, off);
    if (lane == 0) out_logits[gw] = s;
}

// ---------------- launch ----------------
extern "C" void kernel_launch(void* const* d_in, const int* in_sizes, int n_in,
                              void* d_out, int out_size) {
    const void* p_lit   = d_in[0];
    const void* p_mask  = d_in[1];
    const void* p_alpha = d_in[2];
    for (int i = 0; i < n_in; ++i) {
        if (in_sizes[i] == B * D * L)  p_lit   = d_in[i];
        else if (in_sizes[i] == M * D) p_mask  = d_in[i];
        else if (in_sizes[i] == M)     p_alpha = d_in[i];
    }
    const float* literals = (const float*)p_lit;
    const float* alpha    = (const float*)p_alpha;

    float* out_map    = (float*)d_out;                 // [B,M,L]
    float* out_or     = out_map + (size_t)B * M * L;   // [B,M]
    float* out_logits = out_or + (size_t)B * M;        // [B,CC]

    prep_kernel<<<PREP_BLOCKS, 256>>>(literals, p_mask);

    dim3 cgrid(M / 8, B / 4);
    clause_kernel<<<cgrid, 256>>>(out_map, out_or);

    int lw = B * CC;
    logits_kernel<<<(lw * 32 + 255) / 256, 256>>>(alpha, out_logits);
}

// round 6
// speedup vs baseline: 4.1736x; 1.0756x over previous
#include <cuda_runtime.h>
#include <cstdint>

// Problem constants (fixed by the reference)
#define B   32
#define D   576
#define L   196
#define CC  10
#define K   256
#define M   (CC * K)          // 2560
#define NW  7                 // valid packed words per (b,d) row
#define NWP 8                 // padded words (for [d][b][8] layout)
#define MAXSEL 64             // max selected literals per clause (mean ~11.5)
#define NCHUNK (D / 32)       // 18 mask chunks per clause row

#define ROWS_PER_WARP 4
// prep kernel block roles
#define LIST_BLOCKS   (M / 8)                                  // 320
#define PACK_WARPS    ((B * D) / ROWS_PER_WARP)                // 4608
#define PACK_BLOCKS   (PACK_WARPS / 8)                         // 576
#define PREP_BLOCKS   (1 + LIST_BLOCKS + PACK_BLOCKS)          // 897

// ---------------- scratch (no allocation allowed) ----------------
// litbits layout: word index = d*(B*NWP) + b*NWP + w  -> clause gathers hit ONE line
__device__ uint32_t      g_litbits[D * B * NWP];  // 576 KB (L2-resident)
__device__ int16_t       g_idx[M * MAXSEL];       // per-clause selected d (padded)
__device__ int           g_cnt[M];                // per-clause count (mult of 4)
__device__ unsigned char g_or[B * M];             // clause_or bits for logits
__device__ int           g_mask_dtype;            // 0=uint8, 1=float32, 2=int32
__device__ volatile int  g_dt_ready;              // detect-done flag (monotonic)

// ---------------- kernel 1: fused prep (detect | list | pack) ----------------
__global__ void __launch_bounds__(256) prep_kernel(const float* __restrict__ lit,
                                                   const void*  __restrict__ mask) {
    int lane = threadIdx.x & 31;
    int wblk = threadIdx.x >> 5;

    if (blockIdx.x == 0) {
        // ---- detect: mask values are 0/1 booleans; as 32-bit words:
        //   float32 -> {0, 0x3F800000}; int32 -> {0,1}; uint8 -> packed bytes
        __shared__ int s_float, s_multi;
        if (threadIdx.x == 0) { s_float = 0; s_multi = 0; }
        __syncthreads();
        const uint32_t* w = (const uint32_t*)mask;
        for (int i = threadIdx.x; i < 4096; i += blockDim.x) {
            uint32_t v = w[i];
            if (v == 0x3F800000u) s_float = 1;            // benign race
            else if (v != 0u && v != 1u) s_multi = 1;
        }
        __syncthreads();
        if (threadIdx.x == 0) {
            g_mask_dtype = s_float ? 1 : (s_multi ? 0 : 2);
            __threadfence();
            g_dt_ready = 1;
        }
        return;
    }

    if (blockIdx.x <= LIST_BLOCKS) {
        // ---- list: warp per clause. Spin on dtype first (block 0 is wave-1
        // resident -> no deadlock; value is input-deterministic across graph
        // replays), THEN issue the whole row's loads upfront (MLP=18) so the
        // ballot/popc chain runs on registers, not on serialized DRAM trips.
        int m = (blockIdx.x - 1) * 8 + wblk;
        while (g_dt_ready == 0) { __nanosleep(32); }
        __threadfence();
        int dt = g_mask_dtype;

        int cnt = 0;
        int firstd = -1;
        if (dt != 0) {
            // 4-byte elements (float32 or int32): selected <=> raw word != 0
            const uint32_t* row32 = (const uint32_t*)mask + (size_t)m * D;
            uint32_t wv[NCHUNK];
#pragma unroll
            for (int j = 0; j < NCHUNK; ++j)
                wv[j] = row32[j * 32 + lane];             // all issued upfront
#pragma unroll
            for (int j = 0; j < NCHUNK; ++j) {
                bool sel = (wv[j] != 0u);
                unsigned bal = __ballot_sync(0xFFFFFFFFu, sel);
                if (firstd < 0 && bal) firstd = j * 32 + __ffs(bal) - 1;
                int pos = cnt + __popc(bal & ((1u << lane) - 1u));
                if (sel && pos < MAXSEL) g_idx[m * MAXSEL + pos] = (int16_t)(j * 32 + lane);
                cnt += __popc(bal);
            }
        } else {
            // uint8 fallback (unlikely per harness dtypes)
            const unsigned char* bm = (const unsigned char*)mask + (size_t)m * D;
            for (int c = 0; c < D; c += 32) {
                int d = c + lane;
                bool sel = (bm[d] != 0);
                unsigned bal = __ballot_sync(0xFFFFFFFFu, sel);
                if (firstd < 0 && bal) firstd = c + __ffs(bal) - 1;
                int pos = cnt + __popc(bal & ((1u << lane) - 1u));
                if (sel && pos < MAXSEL) g_idx[m * MAXSEL + pos] = (int16_t)d;
                cnt += __popc(bal);
            }
        }
        if (cnt > MAXSEL) cnt = MAXSEL;
        int cnt4 = (cnt + 3) & ~3;
        if (lane < cnt4 - cnt) g_idx[m * MAXSEL + cnt + lane] = (int16_t)firstd;
        if (lane == 0) g_cnt[m] = cnt4;
        return;
    }

    // ---- pack: warp handles ROWS_PER_WARP consecutive (b,d) rows.
    // ALL 28 loads issued upfront (MLP=28) -> one DRAM wait amortized over
    // 4 rows, then pure register ballots. Transposed store layout [d][b][8].
    int pw   = (blockIdx.x - 1 - LIST_BLOCKS) * 8 + wblk;     // 0 .. PACK_WARPS-1
    int row0 = pw * ROWS_PER_WARP;                            // (b*D + d) index
    int b = row0 / D;
    int d = row0 - b * D;

    const float* rp = lit + (size_t)row0 * L;
    float v[ROWS_PER_WARP][NW];
#pragma unroll
    for (int r = 0; r < ROWS_PER_WARP; ++r)
#pragma unroll
        for (int w = 0; w < NW; ++w) {
            int l = w * 32 + lane;
            v[r][w] = (l < L) ? rp[(size_t)r * L + l] : 0.0f;
        }

#pragma unroll
    for (int r = 0; r < ROWS_PER_WARP; ++r) {
        unsigned ws[NW];
#pragma unroll
        for (int w = 0; w < NW; ++w)
            ws[w] = __ballot_sync(0xFFFFFFFFu, v[r][w] > 0.5f);

        unsigned out = ws[0];
        if (lane == 1) out = ws[1];
        if (lane == 2) out = ws[2];
        if (lane == 3) out = ws[3];
        if (lane == 4) out = ws[4];
        if (lane == 5) out = ws[5];
        if (lane == 6) out = ws[6];
        if (lane < NW) g_litbits[d * (B * NWP) + b * NWP + lane] = out;

        if (++d == D) { d = 0; ++b; }
    }
}

// ---------------- kernel 2: clause AND-reduce + outputs ----------------
// One warp: clause m x 4 batches. Lanes 0..27 = (bq 0..3) x (w 0..6).
// Each gather LDG (28 lanes) hits exactly one 128B line of g_litbits.
__global__ void clause_kernel(float* __restrict__ out_map,
                              float* __restrict__ out_or) {
    int wblk = threadIdx.x >> 5;
    int lane = threadIdx.x & 31;
    int m  = blockIdx.x * 8 + wblk;                   // 320 x 8 = 2560
    int b0 = blockIdx.y * 4;                          // 8 x 4 = 32

    int bq = lane / 7;                                // 0..4 (4 => idle)
    int w  = lane - bq * 7;

    int cnt4 = g_cnt[m];
    const int16_t* idxp = g_idx + m * MAXSEL;

    unsigned acc = 0xFFFFFFFFu;
    if (lane < 28) {
        const uint32_t* base = g_litbits + (b0 + bq) * NWP + w;
        for (int i = 0; i < cnt4; i += 4) {
            uint64_t q = *(const uint64_t*)(idxp + i);
            int d0 = (int)(q & 0xFFFFu);
            int d1 = (int)((q >> 16) & 0xFFFFu);
            int d2 = (int)((q >> 32) & 0xFFFFu);
            int d3 = (int)((q >> 48) & 0xFFFFu);
            unsigned a0 = base[d0 * (B * NWP)];
            unsigned a1 = base[d1 * (B * NWP)];
            unsigned a2 = base[d2 * (B * NWP)];
            unsigned a3 = base[d3 * (B * NWP)];
            acc &= (a0 & a1) & (a2 & a3);
        }
        if (w == 6) acc &= 0xFu;                      // 4 valid bits in word 6
    }

    // ---- clause_map stores: per batch row, 49 float4 slots ----
#pragma unroll
    for (int q = 0; q < 4; ++q) {
        uint4* row = (uint4*)(out_map + ((size_t)(b0 + q) * M + m) * L);
        unsigned w0 = __shfl_sync(0xFFFFFFFFu, acc, q * 7 + (lane >> 3));
        unsigned n0 = (w0 >> ((lane & 7) * 4)) & 0xFu;
        uint4 vv;
        vv.x = (n0 & 1u)        * 0x3F800000u;
        vv.y = ((n0 >> 1) & 1u) * 0x3F800000u;
        vv.z = ((n0 >> 2) & 1u) * 0x3F800000u;
        vv.w = ((n0 >> 3) & 1u) * 0x3F800000u;
        row[lane] = vv;
        unsigned w1 = __shfl_sync(0xFFFFFFFFu, acc, q * 7 + 4 + (lane >> 3));
        if (lane < 17) {
            unsigned n1 = (w1 >> ((lane & 7) * 4)) & 0xFu;
            uint4 u;
            u.x = (n1 & 1u)        * 0x3F800000u;
            u.y = ((n1 >> 1) & 1u) * 0x3F800000u;
            u.z = ((n1 >> 2) & 1u) * 0x3F800000u;
            u.w = ((n1 >> 3) & 1u) * 0x3F800000u;
            row[32 + lane] = u;
        }
    }

    // ---- clause_or ----
    bool nz = (lane < 28) && (acc != 0u);
    unsigned bal = __ballot_sync(0xFFFFFFFFu, nz);
    if (lane < 4) {
        unsigned any = (bal >> (lane * 7)) & 0x7Fu;
        int gi = (b0 + lane) * M + m;
        out_or[gi] = any ? 1.0f : 0.0f;
        g_or[gi]   = any ? 1 : 0;
    }
}

// ---------------- kernel 3: weighted vote logits ----------------
__global__ void logits_kernel(const float* __restrict__ alpha,
                              float* __restrict__ out_logits) {
    int gw   = (blockIdx.x * blockDim.x + threadIdx.x) >> 5;
    int lane = threadIdx.x & 31;
    if (gw >= B * CC) return;
    int b = gw / CC;
    int c = gw - b * CC;

    float s = 0.0f;
    for (int k = lane; k < K; k += 32) {
        int idx = c * K + k;
        float z = g_or[b * M + idx] ? 1.0f : 0.0f;
        float sg = (k < (K / 2)) ? 1.0f : -1.0f;
        s += z * alpha[idx] * sg;
    }
#pragma unroll
    for (int off = 16; off; off >>= 1) s += __shfl_xor_sync(0xFFFFFFFFu, s, off);
    if (lane == 0) out_logits[gw] = s;
}

// ---------------- launch ----------------
extern "C" void kernel_launch(void* const* d_in, const int* in_sizes, int n_in,
                              void* d_out, int out_size) {
    const void* p_lit   = d_in[0];
    const void* p_mask  = d_in[1];
    const void* p_alpha = d_in[2];
    for (int i = 0; i < n_in; ++i) {
        if (in_sizes[i] == B * D * L)  p_lit   = d_in[i];
        else if (in_sizes[i] == M * D) p_mask  = d_in[i];
        else if (in_sizes[i] == M)     p_alpha = d_in[i];
    }
    const float* literals = (const float*)p_lit;
    const float* alpha    = (const float*)p_alpha;

    float* out_map    = (float*)d_out;                 // [B,M,L]
    float* out_or     = out_map + (size_t)B * M * L;   // [B,M]
    float* out_logits = out_or + (size_t)B * M;        // [B,CC]

    prep_kernel<<<PREP_BLOCKS, 256>>>(literals, p_mask);

    dim3 cgrid(M / 8, B / 4);
    clause_kernel<<<cgrid, 256>>>(out_map, out_or);

    int lw = B * CC;
    logits_kernel<<<(lw * 32 + 255) / 256, 256>>>(alpha, out_logits);
}

// round 7
// speedup vs baseline: 4.1934x; 1.0047x over previous
#include <cuda_runtime.h>
#include <cstdint>

// Problem constants (fixed by the reference)
#define B   32
#define D   576
#define L   196
#define CC  10
#define K   256
#define M   (CC * K)          // 2560
#define NWP 8                 // packed words per (b,d) row (all 8 used now)
#define MAXSEL 64             // max selected literals per clause (mean ~11.5)

// Bit layout (fixed permutation, consistent between pack & clause kernels):
//   words 0..3 : element l = 4*j + k   (l <  128)  -> word k, bit j (j in 0..31)
//   words 4..7 : element l = 128+4*j+k (l in 128..195) -> word 4+k, bit j (j in 0..16)

#define ROWS_PER_WARP 4
#define LIST_BLOCKS   (M / 8)                                  // 320
#define PACK_WARPS    ((B * D) / ROWS_PER_WARP)                // 4608
#define PACK_BLOCKS   (PACK_WARPS / 8)                         // 576
#define PREP_BLOCKS   (1 + LIST_BLOCKS + PACK_BLOCKS)          // 897

// ---------------- scratch (no allocation allowed) ----------------
// litbits word index = d*(B*NWP) + b*NWP + w  -> clause gathers hit ONE 128B line
__device__ uint32_t      g_litbits[D * B * NWP];  // 576 KB (L2-resident)
__device__ int16_t       g_idx[M * MAXSEL];       // per-clause selected d (padded)
__device__ int           g_cnt[M];                // per-clause count (mult of 4)
__device__ unsigned char g_or[B * M];             // clause_or bits for logits
__device__ int           g_mask_dtype;            // 0=uint8, 1=float32, 2=int32
__device__ volatile int  g_dt_ready;              // detect-done flag (monotonic)

// ---------------- kernel 1: fused prep (detect | list | pack) ----------------
__global__ void __launch_bounds__(256, 4) prep_kernel(const float* __restrict__ lit,
                                                      const void*  __restrict__ mask) {
    int lane = threadIdx.x & 31;
    int wblk = threadIdx.x >> 5;

    if (blockIdx.x == 0) {
        // ---- detect: mask values are 0/1 booleans; as 32-bit words:
        //   float32 -> {0, 0x3F800000}; int32 -> {0,1}; uint8 -> packed bytes
        __shared__ int s_float, s_multi;
        if (threadIdx.x == 0) { s_float = 0; s_multi = 0; }
        __syncthreads();
        const uint32_t* w = (const uint32_t*)mask;
        for (int i = threadIdx.x; i < 4096; i += blockDim.x) {
            uint32_t v = w[i];
            if (v == 0x3F800000u) s_float = 1;            // benign race
            else if (v != 0u && v != 1u) s_multi = 1;
        }
        __syncthreads();
        if (threadIdx.x == 0) {
            g_mask_dtype = s_float ? 1 : (s_multi ? 0 : 2);
            __threadfence();
            g_dt_ready = 1;
        }
        return;
    }

    if (blockIdx.x <= LIST_BLOCKS) {
        // ---- list: warp per clause. Spin on dtype (block 0 is wave-1 resident
        // -> no deadlock; value is input-deterministic across graph replays),
        // then load the whole 2304B row as 5 uint4 per lane (MLP, wide).
        // Compaction order is interleaved -- harmless, AND is commutative.
        int m = (blockIdx.x - 1) * 8 + wblk;
        while (g_dt_ready == 0) { __nanosleep(32); }
        __threadfence();
        int dt = g_mask_dtype;

        int cnt = 0;
        int firstd = -1;
        if (dt != 0) {
            // 4-byte elements (float32/int32): selected <=> raw word != 0
            const uint4* row4 = (const uint4*)((const uint32_t*)mask + (size_t)m * D);
            uint4 wv[5];
#pragma unroll
            for (int c = 0; c < 4; ++c) wv[c] = row4[c * 32 + lane];
            wv[4] = (lane < 16) ? row4[128 + lane] : make_uint4(0, 0, 0, 0);
#pragma unroll
            for (int c = 0; c < 5; ++c) {
                uint32_t vk[4] = { wv[c].x, wv[c].y, wv[c].z, wv[c].w };
#pragma unroll
                for (int k = 0; k < 4; ++k) {
                    bool sel = (vk[k] != 0u);
                    unsigned bal = __ballot_sync(0xFFFFFFFFu, sel);
                    if (firstd < 0 && bal) firstd = c * 128 + 4 * (__ffs(bal) - 1) + k;
                    int pos = cnt + __popc(bal & ((1u << lane) - 1u));
                    int d = c * 128 + 4 * lane + k;
                    if (sel && pos < MAXSEL) g_idx[m * MAXSEL + pos] = (int16_t)d;
                    cnt += __popc(bal);
                }
            }
        } else {
            // uint8 fallback (unlikely per harness dtypes)
            const unsigned char* bm = (const unsigned char*)mask + (size_t)m * D;
            for (int c = 0; c < D; c += 32) {
                int d = c + lane;
                bool sel = (bm[d] != 0);
                unsigned bal = __ballot_sync(0xFFFFFFFFu, sel);
                if (firstd < 0 && bal) firstd = c + __ffs(bal) - 1;
                int pos = cnt + __popc(bal & ((1u << lane) - 1u));
                if (sel && pos < MAXSEL) g_idx[m * MAXSEL + pos] = (int16_t)d;
                cnt += __popc(bal);
            }
        }
        if (cnt > MAXSEL) cnt = MAXSEL;
        int cnt4 = (cnt + 3) & ~3;
        if (lane < cnt4 - cnt) g_idx[m * MAXSEL + cnt + lane] = (int16_t)firstd;
        if (lane == 0) g_cnt[m] = cnt4;
        return;
    }

    // ---- pack: warp handles 4 consecutive (b,d) rows. 2 x LDG.128 per row,
    // ALL 8 wide loads issued upfront (kept live; launch_bounds allows 64 regs),
    // then register-only ballots. Store layout [d][b][8] words.
    int pw   = (blockIdx.x - 1 - LIST_BLOCKS) * 8 + wblk;     // 0 .. PACK_WARPS-1
    int row0 = pw * ROWS_PER_WARP;                            // (b*D + d) index
    int b = row0 / D;
    int d = row0 - b * D;

    float4 ga[ROWS_PER_WARP], gb[ROWS_PER_WARP];
#pragma unroll
    for (int r = 0; r < ROWS_PER_WARP; ++r) {
        const float4* rr = (const float4*)(lit + (size_t)(row0 + r) * L);
        ga[r] = rr[lane];                                     // elements 4*lane..+3
        gb[r] = (lane < 17) ? rr[32 + lane]                   // elements 128+4*lane..+3
                            : make_float4(0.f, 0.f, 0.f, 0.f);
    }

#pragma unroll
    for (int r = 0; r < ROWS_PER_WARP; ++r) {
        unsigned w0 = __ballot_sync(0xFFFFFFFFu, ga[r].x > 0.5f);
        unsigned w1 = __ballot_sync(0xFFFFFFFFu, ga[r].y > 0.5f);
        unsigned w2 = __ballot_sync(0xFFFFFFFFu, ga[r].z > 0.5f);
        unsigned w3 = __ballot_sync(0xFFFFFFFFu, ga[r].w > 0.5f);
        unsigned w4 = __ballot_sync(0xFFFFFFFFu, gb[r].x > 0.5f);
        unsigned w5 = __ballot_sync(0xFFFFFFFFu, gb[r].y > 0.5f);
        unsigned w6 = __ballot_sync(0xFFFFFFFFu, gb[r].z > 0.5f);
        unsigned w7 = __ballot_sync(0xFFFFFFFFu, gb[r].w > 0.5f);

        unsigned out = w0;
        if (lane == 1) out = w1;
        if (lane == 2) out = w2;
        if (lane == 3) out = w3;
        if (lane == 4) out = w4;
        if (lane == 5) out = w5;
        if (lane == 6) out = w6;
        if (lane == 7) out = w7;
        if (lane < NWP) g_litbits[d * (B * NWP) + b * NWP + lane] = out;

        if (++d == D) { d = 0; ++b; }
    }
}

// ---------------- kernel 2: clause AND-reduce + outputs ----------------
// One warp: clause m x 4 batches. Lanes = (bq 0..3) x (w 0..7), all 32 active.
// Each gather LDG (32 lanes, same d) hits exactly one 128B line of g_litbits.
__global__ void clause_kernel(float* __restrict__ out_map,
                              float* __restrict__ out_or) {
    int wblk = threadIdx.x >> 5;
    int lane = threadIdx.x & 31;
    int m  = blockIdx.x * 8 + wblk;                   // 320 x 8 = 2560
    int b0 = blockIdx.y * 4;                          // 8 x 4 = 32

    int bq = lane >> 3;                               // 0..3
    int w  = lane & 7;                                // 0..7

    int cnt4 = g_cnt[m];
    const int16_t* idxp = g_idx + m * MAXSEL;

    unsigned acc = 0xFFFFFFFFu;
    {
        const uint32_t* base = g_litbits + (b0 + bq) * NWP + w;
        for (int i = 0; i < cnt4; i += 4) {
            uint64_t q = *(const uint64_t*)(idxp + i);
            int d0 = (int)(q & 0xFFFFu);
            int d1 = (int)((q >> 16) & 0xFFFFu);
            int d2 = (int)((q >> 32) & 0xFFFFu);
            int d3 = (int)((q >> 48) & 0xFFFFu);
            unsigned a0 = base[d0 * (B * NWP)];
            unsigned a1 = base[d1 * (B * NWP)];
            unsigned a2 = base[d2 * (B * NWP)];
            unsigned a3 = base[d3 * (B * NWP)];
            acc &= (a0 & a1) & (a2 & a3);
        }
        if (w >= 4) acc &= 0x1FFFFu;                  // group-B words: 17 valid bits
    }

    // ---- clause_map stores: per batch row, 49 float4 slots ----
    //   slot s<32 : elements 4s+k   = word k   bit s
    //   slot 32+j : elements 128+4j+k = word 4+k bit j   (j = lane, 0..16)
#pragma unroll
    for (int q = 0; q < 4; ++q) {
        uint4* row = (uint4*)(out_map + ((size_t)(b0 + q) * M + m) * L);
        unsigned w0 = __shfl_sync(0xFFFFFFFFu, acc, q * 8 + 0);
        unsigned w1 = __shfl_sync(0xFFFFFFFFu, acc, q * 8 + 1);
        unsigned w2 = __shfl_sync(0xFFFFFFFFu, acc, q * 8 + 2);
        unsigned w3 = __shfl_sync(0xFFFFFFFFu, acc, q * 8 + 3);
        uint4 v;
        v.x = ((w0 >> lane) & 1u) * 0x3F800000u;
        v.y = ((w1 >> lane) & 1u) * 0x3F800000u;
        v.z = ((w2 >> lane) & 1u) * 0x3F800000u;
        v.w = ((w3 >> lane) & 1u) * 0x3F800000u;
        row[lane] = v;
        unsigned w4 = __shfl_sync(0xFFFFFFFFu, acc, q * 8 + 4);
        unsigned w5 = __shfl_sync(0xFFFFFFFFu, acc, q * 8 + 5);
        unsigned w6 = __shfl_sync(0xFFFFFFFFu, acc, q * 8 + 6);
        unsigned w7 = __shfl_sync(0xFFFFFFFFu, acc, q * 8 + 7);
        if (lane < 17) {
            uint4 u;
            u.x = ((w4 >> lane) & 1u) * 0x3F800000u;
            u.y = ((w5 >> lane) & 1u) * 0x3F800000u;
            u.z = ((w6 >> lane) & 1u) * 0x3F800000u;
            u.w = ((w7 >> lane) & 1u) * 0x3F800000u;
            row[32 + lane] = u;
        }
    }

    // ---- clause_or ----
    bool nz = (acc != 0u);
    unsigned bal = __ballot_sync(0xFFFFFFFFu, nz);
    if (lane < 4) {
        unsigned any = (bal >> (lane * 8)) & 0xFFu;
        int gi = (b0 + lane) * M + m;
        out_or[gi] = any ? 1.0f : 0.0f;
        g_or[gi]   = any ? 1 : 0;
    }
}

// ---------------- kernel 3: weighted vote logits ----------------
__global__ void logits_kernel(const float* __restrict__ alpha,
                              float* __restrict__ out_logits) {
    int gw   = (blockIdx.x * blockDim.x + threadIdx.x) >> 5;
    int lane = threadIdx.x & 31;
    if (gw >= B * CC) return;
    int b = gw / CC;
    int c = gw - b * CC;

    float s = 0.0f;
    for (int k = lane; k < K; k += 32) {
        int idx = c * K + k;
        float z = g_or[b * M + idx] ? 1.0f : 0.0f;
        float sg = (k < (K / 2)) ? 1.0f : -1.0f;
        s += z * alpha[idx] * sg;
    }
#pragma unroll
    for (int off = 16; off; off >>= 1) s += __shfl_xor_sync(0xFFFFFFFFu, s, off);
    if (lane == 0) out_logits[gw] = s;
}

// ---------------- launch ----------------
extern "C" void kernel_launch(void* const* d_in, const int* in_sizes, int n_in,
                              void* d_out, int out_size) {
    const void* p_lit   = d_in[0];
    const void* p_mask  = d_in[1];
    const void* p_alpha = d_in[2];
    for (int i = 0; i < n_in; ++i) {
        if (in_sizes[i] == B * D * L)  p_lit   = d_in[i];
        else if (in_sizes[i] == M * D) p_mask  = d_in[i];
        else if (in_sizes[i] == M)     p_alpha = d_in[i];
    }
    const float* literals = (const float*)p_lit;
    const float* alpha    = (const float*)p_alpha;

    float* out_map    = (float*)d_out;                 // [B,M,L]
    float* out_or     = out_map + (size_t)B * M * L;   // [B,M]
    float* out_logits = out_or + (size_t)B * M;        // [B,CC]

    prep_kernel<<<PREP_BLOCKS, 256>>>(literals, p_mask);

    dim3 cgrid(M / 8, B / 4);
    clause_kernel<<<cgrid, 256>>>(out_map, out_or);

    int lw = B * CC;
    logits_kernel<<<(lw * 32 + 255) / 256, 256>>>(alpha, out_logits);
}